// round 9
// baseline (speedup 1.0000x reference)
#include <cuda_runtime.h>
#include <cstdint>

#define BB 2
#define SS 2048
#define DM 1024
#define HH 16
#define DH 64
#define NEG_MASK (-9e10f)

__device__ float g_q[BB * HH * SS * DH];
__device__ float g_k[BB * HH * SS * DH];
__device__ float g_v[BB * HH * SS * DH];
__device__ float g_ctx[BB * SS * DM];

__device__ __forceinline__ uint32_t f2tf(float x) {
    uint32_t r;
    asm volatile("cvt.rna.tf32.f32 %0, %1;" : "=r"(r) : "f"(x));
    return r;
}

__device__ __forceinline__ void mma8(float* d, const uint32_t* a, uint32_t b0, uint32_t b1) {
    asm volatile(
        "mma.sync.aligned.m16n8k8.row.col.f32.tf32.tf32.f32 "
        "{%0,%1,%2,%3}, {%4,%5,%6,%7}, {%8,%9}, {%0,%1,%2,%3};\n"
        : "+f"(d[0]), "+f"(d[1]), "+f"(d[2]), "+f"(d[3])
        : "r"(a[0]), "r"(a[1]), "r"(a[2]), "r"(a[3]), "r"(b0), "r"(b1));
}

// ---------------------------------------------------------------
// NT GEMM (tf32, register-prefetch pipelined)
// ---------------------------------------------------------------
#define GBK 32
#define GPAD 36

__global__ __launch_bounds__(256, 1) void gemm_tc_kernel(
    const float* __restrict__ A, const float* __restrict__ W,
    const float* __restrict__ bias, float* __restrict__ C, int split)
{
    __shared__ uint32_t As[128 * GPAD];
    __shared__ uint32_t Ws[128 * GPAD];

    const int tid  = threadIdx.x;
    const int warp = tid >> 5;
    const int lane = tid & 31;
    const int g    = lane >> 2;
    const int t4   = lane & 3;
    const int wm   = warp & 1;
    const int wn   = warp >> 1;
    const int m0   = blockIdx.y * 128;
    const int n0   = blockIdx.x * 128;

    float acc[4][4][4];
#pragma unroll
    for (int mt = 0; mt < 4; mt++)
#pragma unroll
        for (int nt = 0; nt < 4; nt++)
#pragma unroll
            for (int r = 0; r < 4; r++) acc[mt][nt][r] = 0.f;

    const float* Ap = A + (size_t)m0 * DM;
    const float* Wp = W + (size_t)n0 * DM;

    // stage k0 = 0
#pragma unroll
    for (int i = 0; i < 4; i++) {
        int idx = tid + i * 256;
        int r   = idx >> 3;
        int c4  = (idx & 7) * 4;
        float4 a = *(const float4*)(Ap + (size_t)r * DM + c4);
        As[r * GPAD + c4 + 0] = f2tf(a.x); As[r * GPAD + c4 + 1] = f2tf(a.y);
        As[r * GPAD + c4 + 2] = f2tf(a.z); As[r * GPAD + c4 + 3] = f2tf(a.w);
        float4 w = *(const float4*)(Wp + (size_t)r * DM + c4);
        Ws[r * GPAD + c4 + 0] = f2tf(w.x); Ws[r * GPAD + c4 + 1] = f2tf(w.y);
        Ws[r * GPAD + c4 + 2] = f2tf(w.z); Ws[r * GPAD + c4 + 3] = f2tf(w.w);
    }
    __syncthreads();

    float4 pa[4], pw[4];
    for (int k0 = 0; k0 < DM; k0 += GBK) {
        const bool more = (k0 + GBK) < DM;
        if (more) {
#pragma unroll
            for (int i = 0; i < 4; i++) {
                int idx = tid + i * 256;
                int r   = idx >> 3;
                int c4  = (idx & 7) * 4;
                pa[i] = *(const float4*)(Ap + (size_t)r * DM + k0 + GBK + c4);
                pw[i] = *(const float4*)(Wp + (size_t)r * DM + k0 + GBK + c4);
            }
        }

#pragma unroll
        for (int ks = 0; ks < GBK / 8; ks++) {
            const int kc = ks * 8 + t4;
            uint32_t af[4][4];
#pragma unroll
            for (int mt = 0; mt < 4; mt++) {
                int row = wm * 64 + mt * 16 + g;
                af[mt][0] = As[row * GPAD + kc];
                af[mt][1] = As[(row + 8) * GPAD + kc];
                af[mt][2] = As[row * GPAD + kc + 4];
                af[mt][3] = As[(row + 8) * GPAD + kc + 4];
            }
#pragma unroll
            for (int nt = 0; nt < 4; nt++) {
                int col = wn * 32 + nt * 8 + g;
                uint32_t b0 = Ws[col * GPAD + kc];
                uint32_t b1 = Ws[col * GPAD + kc + 4];
#pragma unroll
                for (int mt = 0; mt < 4; mt++)
                    mma8(acc[mt][nt], af[mt], b0, b1);
            }
        }
        __syncthreads();
        if (more) {
#pragma unroll
            for (int i = 0; i < 4; i++) {
                int idx = tid + i * 256;
                int r   = idx >> 3;
                int c4  = (idx & 7) * 4;
                As[r * GPAD + c4 + 0] = f2tf(pa[i].x); As[r * GPAD + c4 + 1] = f2tf(pa[i].y);
                As[r * GPAD + c4 + 2] = f2tf(pa[i].z); As[r * GPAD + c4 + 3] = f2tf(pa[i].w);
                Ws[r * GPAD + c4 + 0] = f2tf(pw[i].x); Ws[r * GPAD + c4 + 1] = f2tf(pw[i].y);
                Ws[r * GPAD + c4 + 2] = f2tf(pw[i].z); Ws[r * GPAD + c4 + 3] = f2tf(pw[i].w);
            }
            __syncthreads();
        }
    }

#pragma unroll
    for (int mt = 0; mt < 4; mt++) {
        int r0 = m0 + wm * 64 + mt * 16 + g;
        int r1 = r0 + 8;
#pragma unroll
        for (int nt = 0; nt < 4; nt++) {
            int c = n0 + wn * 32 + nt * 8 + 2 * t4;
            float2 bi = *(const float2*)(bias + c);
            float v00 = acc[mt][nt][0] + bi.x;
            float v01 = acc[mt][nt][1] + bi.y;
            float v10 = acc[mt][nt][2] + bi.x;
            float v11 = acc[mt][nt][3] + bi.y;
            if (split) {
                int h  = c >> 6;
                int dh = c & 63;
                int b0i = r0 >> 11, s0 = r0 & 2047;
                int b1i = r1 >> 11, s1 = r1 & 2047;
                float* p0 = (float*)C + (((size_t)b0i * HH + h) * SS + s0) * DH + dh;
                float* p1 = (float*)C + (((size_t)b1i * HH + h) * SS + s1) * DH + dh;
                p0[0] = v00; p0[1] = v01;
                p1[0] = v10; p1[1] = v11;
            } else {
                *(float2*)(C + (size_t)r0 * DM + c) = make_float2(v00, v01);
                *(float2*)(C + (size_t)r1 * DM + c) = make_float2(v10, v11);
            }
        }
    }
}

// ---------------------------------------------------------------
// Flash attention, fragment-packed smem + prefetch pipeline.
// 8 warps x 16 q-rows. Layouts:
//  Qp[blk][ks][lane][4]   (LDS.128 A-frag), 8192 u32
//  Kp[ks][t4][n*2+p], stride t4 = 136, ks = 544 (LDS.64 B-frag), 4352 u32
//  Vp same structure, 4352 u32
//  Ps[128][76] (unchanged), 9728 u32
// ---------------------------------------------------------------
#define PP 76
#define KSTR 544
#define TSTR 136
#define ATT_SMEM_U32 (8192 + 4352 + 4352 + 128 * PP)

__global__ __launch_bounds__(256) void attn_tc_kernel(
    const float* __restrict__ q, const float* __restrict__ k,
    const float* __restrict__ v, const uint32_t* __restrict__ mask,
    float* __restrict__ ctx)
{
    extern __shared__ uint32_t su[];
    uint32_t* Qp = su;
    uint32_t* Kp = Qp + 8192;
    uint32_t* Vp = Kp + 4352;
    uint32_t* Ps = Vp + 4352;

    const int tid  = threadIdx.x;
    const int warp = tid >> 5;
    const int lane = tid & 31;
    const int g    = lane >> 2;
    const int t4   = lane & 3;
    const int a7   = lane & 7;
    const int b3   = lane >> 3;      // 0..3
    const int qg0  = blockIdx.x * 128;
    const int h    = blockIdx.y;
    const int b    = blockIdx.z;
    const int wrow0 = warp * 16;

    const float* qptr  = q + (((size_t)b * HH + h) * SS + qg0) * DH;
    const float* kbase = k + (((size_t)b * HH + h) * SS) * DH;
    const float* vbase = v + (((size_t)b * HH + h) * SS) * DH;
    const uint32_t* mbase = mask + (size_t)b * SS * SS;

    // ---- stage Q (packed A-frag layout), scaled ----
#pragma unroll
    for (int i = 0; i < 8; i++) {
        int idx = tid + i * 256;
        int r   = idx >> 4;
        int c0  = (idx & 15) * 4;
        float4 a = *(const float4*)(qptr + (size_t)r * DH + c0);
        int blk = r >> 4, gg = r & 7, half = (r >> 3) & 1;
        int ks  = c0 >> 3, chi = (c0 >> 2) & 1;
        int base = ((blk * 8 + ks) * 32 + 4 * gg) * 4 + (half + 2 * chi);
        Qp[base + 0]  = f2tf(a.x * 0.125f);
        Qp[base + 4]  = f2tf(a.y * 0.125f);
        Qp[base + 8]  = f2tf(a.z * 0.125f);
        Qp[base + 12] = f2tf(a.w * 0.125f);
    }

    // ---- stage K/V chunk 0 ----
    {
        const int n = 8 * warp + a7;
#pragma unroll
        for (int i = 0; i < 4; i++) {
            int c0 = 4 * b3 + 16 * i;
            float4 f  = *(const float4*)(kbase + (size_t)n * DH + c0);
            float4 fv = *(const float4*)(vbase + (size_t)n * DH + c0);
            float ka[4] = {f.x, f.y, f.z, f.w};
            float va[4] = {fv.x, fv.y, fv.z, fv.w};
#pragma unroll
            for (int j = 0; j < 4; j++) {
                int vv = (j + a7) & 3;
                int c  = c0 + vv;
                Kp[(c >> 3) * KSTR + vv * TSTR + n * 2 + ((c >> 2) & 1)] = f2tf(ka[vv]);
                Vp[warp * KSTR + (a7 & 3) * TSTR + c * 2 + (a7 >> 2)]    = f2tf(va[vv]);
            }
        }
    }
    __syncthreads();

    float o[8][4];
#pragma unroll
    for (int nt = 0; nt < 8; nt++)
#pragma unroll
        for (int r = 0; r < 4; r++) o[nt][r] = 0.f;
    float mr0 = -1e30f, mr1 = -1e30f, l0 = 0.f, l1 = 0.f;

    const int r0g = qg0 + wrow0 + g;
    const int r1g = r0g + 8;
    const uint32_t* mrow0p = mbase + (size_t)r0g * SS;
    const uint32_t* mrow1p = mbase + (size_t)r1g * SS;

    float4 kf[4], vf[4];

    for (int kt = 0; kt < SS / 64; kt++) {
        const int kg0 = kt * 64;
        const bool more = (kt + 1) < (SS / 64);

        // prefetch next K/V chunk into regs
        if (more) {
            const int n = 8 * warp + a7;
#pragma unroll
            for (int i = 0; i < 4; i++) {
                int c0 = 4 * b3 + 16 * i;
                kf[i] = *(const float4*)(kbase + (size_t)(kg0 + 64 + n) * DH + c0);
                vf[i] = *(const float4*)(vbase + (size_t)(kg0 + 64 + n) * DH + c0);
            }
        }

        // prefetch masks for this chunk
        uint2 mk0[8], mk1[8];
#pragma unroll
        for (int nt = 0; nt < 8; nt++) {
            int c = kg0 + nt * 8 + 2 * t4;
            mk0[nt] = *(const uint2*)(mrow0p + c);
            mk1[nt] = *(const uint2*)(mrow1p + c);
        }

        // ---- S = Q K^T ----
        float s[8][4];
#pragma unroll
        for (int nt = 0; nt < 8; nt++)
#pragma unroll
            for (int r = 0; r < 4; r++) s[nt][r] = 0.f;

#pragma unroll
        for (int ks = 0; ks < 8; ks++) {
            uint4 aq = *(const uint4*)&Qp[((warp * 8 + ks) * 32 + lane) * 4];
            uint32_t af[4] = {aq.x, aq.y, aq.z, aq.w};
            const uint32_t* kb = &Kp[ks * KSTR + t4 * TSTR + g * 2];
#pragma unroll
            for (int nt = 0; nt < 8; nt++) {
                uint2 bb = *(const uint2*)&kb[nt * 16];
                mma8(s[nt], af, bb.x, bb.y);
            }
        }

        // ---- mask + online softmax ----
        float M0 = -1e30f, M1 = -1e30f;
#pragma unroll
        for (int nt = 0; nt < 8; nt++) {
            if (mk0[nt].x) s[nt][0] += NEG_MASK;
            if (mk0[nt].y) s[nt][1] += NEG_MASK;
            if (mk1[nt].x) s[nt][2] += NEG_MASK;
            if (mk1[nt].y) s[nt][3] += NEG_MASK;
            M0 = fmaxf(M0, fmaxf(s[nt][0], s[nt][1]));
            M1 = fmaxf(M1, fmaxf(s[nt][2], s[nt][3]));
        }
        M0 = fmaxf(M0, __shfl_xor_sync(0xffffffffu, M0, 1));
        M0 = fmaxf(M0, __shfl_xor_sync(0xffffffffu, M0, 2));
        M1 = fmaxf(M1, __shfl_xor_sync(0xffffffffu, M1, 1));
        M1 = fmaxf(M1, __shfl_xor_sync(0xffffffffu, M1, 2));

        float mn0 = fmaxf(mr0, M0);
        float mn1 = fmaxf(mr1, M1);
        float al0 = __expf(mr0 - mn0);
        float al1 = __expf(mr1 - mn1);
        mr0 = mn0; mr1 = mn1;

        __syncwarp();
        float sum0 = 0.f, sum1 = 0.f;
#pragma unroll
        for (int nt = 0; nt < 8; nt++) {
            float p00 = __expf(s[nt][0] - mn0);
            float p01 = __expf(s[nt][1] - mn0);
            float p10 = __expf(s[nt][2] - mn1);
            float p11 = __expf(s[nt][3] - mn1);
            sum0 += p00 + p01;
            sum1 += p10 + p11;
            int c = nt * 8 + 2 * t4;
            Ps[(wrow0 + g) * PP + c]         = f2tf(p00);
            Ps[(wrow0 + g) * PP + c + 1]     = f2tf(p01);
            Ps[(wrow0 + 8 + g) * PP + c]     = f2tf(p10);
            Ps[(wrow0 + 8 + g) * PP + c + 1] = f2tf(p11);
        }
        sum0 += __shfl_xor_sync(0xffffffffu, sum0, 1);
        sum0 += __shfl_xor_sync(0xffffffffu, sum0, 2);
        sum1 += __shfl_xor_sync(0xffffffffu, sum1, 1);
        sum1 += __shfl_xor_sync(0xffffffffu, sum1, 2);
        l0 = l0 * al0 + sum0;
        l1 = l1 * al1 + sum1;

#pragma unroll
        for (int nt = 0; nt < 8; nt++) {
            o[nt][0] *= al0; o[nt][1] *= al0;
            o[nt][2] *= al1; o[nt][3] *= al1;
        }
        __syncwarp();

        // ---- O += P V ----
#pragma unroll
        for (int ks = 0; ks < 8; ks++) {
            const int kc = ks * 8;
            uint32_t af[4];
            af[0] = Ps[(wrow0 + g) * PP + kc + t4];
            af[1] = Ps[(wrow0 + 8 + g) * PP + kc + t4];
            af[2] = Ps[(wrow0 + g) * PP + kc + t4 + 4];
            af[3] = Ps[(wrow0 + 8 + g) * PP + kc + t4 + 4];
            const uint32_t* vb = &Vp[ks * KSTR + t4 * TSTR + g * 2];
#pragma unroll
            for (int nt = 0; nt < 8; nt++) {
                uint2 bv = *(const uint2*)&vb[nt * 16];
                mma8(o[nt], af, bv.x, bv.y);
            }
        }

        __syncthreads();   // all warps done reading Kp/Vp
        if (more) {
            const int n = 8 * warp + a7;
#pragma unroll
            for (int i = 0; i < 4; i++) {
                int c0 = 4 * b3 + 16 * i;
                float ka[4] = {kf[i].x, kf[i].y, kf[i].z, kf[i].w};
                float va[4] = {vf[i].x, vf[i].y, vf[i].z, vf[i].w};
#pragma unroll
                for (int j = 0; j < 4; j++) {
                    int vv = (j + a7) & 3;
                    int c  = c0 + vv;
                    Kp[(c >> 3) * KSTR + vv * TSTR + n * 2 + ((c >> 2) & 1)] = f2tf(ka[vv]);
                    Vp[warp * KSTR + (a7 & 3) * TSTR + c * 2 + (a7 >> 2)]    = f2tf(va[vv]);
                }
            }
            __syncthreads();
        }
    }

    // ---- epilogue ----
    float inv0 = 1.f / l0, inv1 = 1.f / l1;
    float* out0 = ctx + ((size_t)b * SS + r0g) * DM + h * DH;
    float* out1 = ctx + ((size_t)b * SS + r1g) * DM + h * DH;
#pragma unroll
    for (int nt = 0; nt < 8; nt++) {
        int c = nt * 8 + 2 * t4;
        *(float2*)(out0 + c) = make_float2(o[nt][0] * inv0, o[nt][1] * inv0);
        *(float2*)(out1 + c) = make_float2(o[nt][2] * inv1, o[nt][3] * inv1);
    }
}

// ---------------------------------------------------------------
extern "C" void kernel_launch(void* const* d_in, const int* in_sizes, int n_in,
                              void* d_out, int out_size)
{
    const float* Q  = (const float*)d_in[0];
    const float* K  = (const float*)d_in[1];
    const float* V  = (const float*)d_in[2];
    const uint32_t* mask = (const uint32_t*)d_in[3];
    const float* Wq = (const float*)d_in[4];
    const float* bq = (const float*)d_in[5];
    const float* Wk = (const float*)d_in[6];
    const float* bk = (const float*)d_in[7];
    const float* Wv = (const float*)d_in[8];
    const float* bv = (const float*)d_in[9];
    const float* Wo = (const float*)d_in[10];
    const float* bo = (const float*)d_in[11];
    float* out = (float*)d_out;

    float *qb, *kb, *vb, *ctx;
    cudaGetSymbolAddress((void**)&qb,  g_q);
    cudaGetSymbolAddress((void**)&kb,  g_k);
    cudaGetSymbolAddress((void**)&vb,  g_v);
    cudaGetSymbolAddress((void**)&ctx, g_ctx);

    dim3 gg(DM / 128, (BB * SS) / 128);
    dim3 tt(256);

    gemm_tc_kernel<<<gg, tt>>>(Q, Wq, bq, qb, 1);
    gemm_tc_kernel<<<gg, tt>>>(K, Wk, bk, kb, 1);
    gemm_tc_kernel<<<gg, tt>>>(V, Wv, bv, vb, 1);

    const int smem = ATT_SMEM_U32 * (int)sizeof(uint32_t);
    cudaFuncSetAttribute(attn_tc_kernel, cudaFuncAttributeMaxDynamicSharedMemorySize, smem);
    attn_tc_kernel<<<dim3(SS / 128, HH, BB), tt, smem>>>(qb, kb, vb, mask, ctx);

    gemm_tc_kernel<<<gg, tt>>>(ctx, Wo, bo, out, 0);
}

// round 10
// speedup vs baseline: 1.0282x; 1.0282x over previous
#include <cuda_runtime.h>
#include <cstdint>

#define BB 2
#define SS 2048
#define DM 1024
#define HH 16
#define DH 64
#define NEG_MASK (-9e10f)

__device__ float g_q[BB * HH * SS * DH];
__device__ float g_k[BB * HH * SS * DH];
__device__ float g_v[BB * HH * SS * DH];
__device__ float g_ctx[BB * SS * DM];

__device__ __forceinline__ uint32_t f2tf(float x) {
    uint32_t r;
    asm volatile("cvt.rna.tf32.f32 %0, %1;" : "=r"(r) : "f"(x));
    return r;
}

__device__ __forceinline__ void mma8(float* d, const uint32_t* a, uint32_t b0, uint32_t b1) {
    asm volatile(
        "mma.sync.aligned.m16n8k8.row.col.f32.tf32.tf32.f32 "
        "{%0,%1,%2,%3}, {%4,%5,%6,%7}, {%8,%9}, {%0,%1,%2,%3};\n"
        : "+f"(d[0]), "+f"(d[1]), "+f"(d[2]), "+f"(d[3])
        : "r"(a[0]), "r"(a[1]), "r"(a[2]), "r"(a[3]), "r"(b0), "r"(b1));
}

// ---------------------------------------------------------------
// NT GEMM (tf32, register-prefetch pipelined) — unchanged (round 9)
// ---------------------------------------------------------------
#define GBK 32
#define GPAD 36

__global__ __launch_bounds__(256, 1) void gemm_tc_kernel(
    const float* __restrict__ A, const float* __restrict__ W,
    const float* __restrict__ bias, float* __restrict__ C, int split)
{
    __shared__ uint32_t As[128 * GPAD];
    __shared__ uint32_t Ws[128 * GPAD];

    const int tid  = threadIdx.x;
    const int warp = tid >> 5;
    const int lane = tid & 31;
    const int g    = lane >> 2;
    const int t4   = lane & 3;
    const int wm   = warp & 1;
    const int wn   = warp >> 1;
    const int m0   = blockIdx.y * 128;
    const int n0   = blockIdx.x * 128;

    float acc[4][4][4];
#pragma unroll
    for (int mt = 0; mt < 4; mt++)
#pragma unroll
        for (int nt = 0; nt < 4; nt++)
#pragma unroll
            for (int r = 0; r < 4; r++) acc[mt][nt][r] = 0.f;

    const float* Ap = A + (size_t)m0 * DM;
    const float* Wp = W + (size_t)n0 * DM;

#pragma unroll
    for (int i = 0; i < 4; i++) {
        int idx = tid + i * 256;
        int r   = idx >> 3;
        int c4  = (idx & 7) * 4;
        float4 a = *(const float4*)(Ap + (size_t)r * DM + c4);
        As[r * GPAD + c4 + 0] = f2tf(a.x); As[r * GPAD + c4 + 1] = f2tf(a.y);
        As[r * GPAD + c4 + 2] = f2tf(a.z); As[r * GPAD + c4 + 3] = f2tf(a.w);
        float4 w = *(const float4*)(Wp + (size_t)r * DM + c4);
        Ws[r * GPAD + c4 + 0] = f2tf(w.x); Ws[r * GPAD + c4 + 1] = f2tf(w.y);
        Ws[r * GPAD + c4 + 2] = f2tf(w.z); Ws[r * GPAD + c4 + 3] = f2tf(w.w);
    }
    __syncthreads();

    float4 pa[4], pw[4];
    for (int k0 = 0; k0 < DM; k0 += GBK) {
        const bool more = (k0 + GBK) < DM;
        if (more) {
#pragma unroll
            for (int i = 0; i < 4; i++) {
                int idx = tid + i * 256;
                int r   = idx >> 3;
                int c4  = (idx & 7) * 4;
                pa[i] = *(const float4*)(Ap + (size_t)r * DM + k0 + GBK + c4);
                pw[i] = *(const float4*)(Wp + (size_t)r * DM + k0 + GBK + c4);
            }
        }

#pragma unroll
        for (int ks = 0; ks < GBK / 8; ks++) {
            const int kc = ks * 8 + t4;
            uint32_t af[4][4];
#pragma unroll
            for (int mt = 0; mt < 4; mt++) {
                int row = wm * 64 + mt * 16 + g;
                af[mt][0] = As[row * GPAD + kc];
                af[mt][1] = As[(row + 8) * GPAD + kc];
                af[mt][2] = As[row * GPAD + kc + 4];
                af[mt][3] = As[(row + 8) * GPAD + kc + 4];
            }
#pragma unroll
            for (int nt = 0; nt < 4; nt++) {
                int col = wn * 32 + nt * 8 + g;
                uint32_t b0 = Ws[col * GPAD + kc];
                uint32_t b1 = Ws[col * GPAD + kc + 4];
#pragma unroll
                for (int mt = 0; mt < 4; mt++)
                    mma8(acc[mt][nt], af[mt], b0, b1);
            }
        }
        __syncthreads();
        if (more) {
#pragma unroll
            for (int i = 0; i < 4; i++) {
                int idx = tid + i * 256;
                int r   = idx >> 3;
                int c4  = (idx & 7) * 4;
                As[r * GPAD + c4 + 0] = f2tf(pa[i].x); As[r * GPAD + c4 + 1] = f2tf(pa[i].y);
                As[r * GPAD + c4 + 2] = f2tf(pa[i].z); As[r * GPAD + c4 + 3] = f2tf(pa[i].w);
                Ws[r * GPAD + c4 + 0] = f2tf(pw[i].x); Ws[r * GPAD + c4 + 1] = f2tf(pw[i].y);
                Ws[r * GPAD + c4 + 2] = f2tf(pw[i].z); Ws[r * GPAD + c4 + 3] = f2tf(pw[i].w);
            }
            __syncthreads();
        }
    }

#pragma unroll
    for (int mt = 0; mt < 4; mt++) {
        int r0 = m0 + wm * 64 + mt * 16 + g;
        int r1 = r0 + 8;
#pragma unroll
        for (int nt = 0; nt < 4; nt++) {
            int c = n0 + wn * 32 + nt * 8 + 2 * t4;
            float2 bi = *(const float2*)(bias + c);
            float v00 = acc[mt][nt][0] + bi.x;
            float v01 = acc[mt][nt][1] + bi.y;
            float v10 = acc[mt][nt][2] + bi.x;
            float v11 = acc[mt][nt][3] + bi.y;
            if (split) {
                int h  = c >> 6;
                int dh = c & 63;
                int b0i = r0 >> 11, s0 = r0 & 2047;
                int b1i = r1 >> 11, s1 = r1 & 2047;
                float* p0 = (float*)C + (((size_t)b0i * HH + h) * SS + s0) * DH + dh;
                float* p1 = (float*)C + (((size_t)b1i * HH + h) * SS + s1) * DH + dh;
                p0[0] = v00; p0[1] = v01;
                p1[0] = v10; p1[1] = v11;
            } else {
                *(float2*)(C + (size_t)r0 * DM + c) = make_float2(v00, v01);
                *(float2*)(C + (size_t)r1 * DM + c) = make_float2(v10, v11);
            }
        }
    }
}

// ---------------------------------------------------------------
// Flash attention (tf32). 8 warps x 16 q-rows, K chunks of 64.
// Smem layouts (all reads conflict-free, all indexing static):
//  Qp: [warpblk][ks][lane] uint4 A-frags                (8192 u32)
//  Kq: word(n,c) = (c>>4)*1024 + n*16 + ((c&3 + n)&3)*4 + ((c>>2)&3)
//      -> uint4 per (ksp, n, t4) = (b0,b1)@ks=2ksp, (b0,b1)@2ksp+1  (4096 u32)
//  Vq: word(kv,d) = (kv>>4)*1024 + d*16 + ((kv&3 + ((d>>2)&3))&3)*4 + ((kv>>2)&3)
//                                                        (4096 u32)
//  Ps: [128][76] P tf32                                  (9728 u32)
// ---------------------------------------------------------------
#define PP 76
#define ATT_SMEM_U32 (8192 + 4096 + 4096 + 128 * PP)

__global__ __launch_bounds__(256) void attn_tc_kernel(
    const float* __restrict__ q, const float* __restrict__ k,
    const float* __restrict__ v, const uint32_t* __restrict__ mask,
    float* __restrict__ ctx)
{
    extern __shared__ uint32_t su[];
    uint32_t* Qp = su;
    uint32_t* Kq = Qp + 8192;
    uint32_t* Vq = Kq + 4096;
    uint32_t* Ps = Vq + 4096;

    const int tid  = threadIdx.x;
    const int warp = tid >> 5;
    const int lane = tid & 31;
    const int g    = lane >> 2;
    const int t4   = lane & 3;
    const int a7   = lane & 7;
    const int b3   = lane >> 3;
    const int qg0  = blockIdx.x * 128;
    const int h    = blockIdx.y;
    const int b    = blockIdx.z;
    const int wrow0 = warp * 16;

    // staging maps
    const int krow  = 8 * warp + a7;                    // K: row, cols 4*b3+16*i
    const int vrow  = 16 * (warp & 3) + (lane >> 1);    // V: row
    const int vcol0 = 32 * (warp >> 2) + 16 * (lane & 1);

    const float* qptr  = q + (((size_t)b * HH + h) * SS + qg0) * DH;
    const float* kbase = k + (((size_t)b * HH + h) * SS) * DH;
    const float* vbase = v + (((size_t)b * HH + h) * SS) * DH;
    const uint32_t* mbase = mask + (size_t)b * SS * SS;

    // ---- stage Q (packed A-frag layout), scaled — static indexing ----
#pragma unroll
    for (int i = 0; i < 8; i++) {
        int idx = tid + i * 256;
        int r   = idx >> 4;
        int c0  = (idx & 15) * 4;
        float4 a = *(const float4*)(qptr + (size_t)r * DH + c0);
        int blk = r >> 4, gg = r & 7, half = (r >> 3) & 1;
        int ks  = c0 >> 3, chi = (c0 >> 2) & 1;
        int base = ((blk * 8 + ks) * 32 + 4 * gg) * 4 + (half + 2 * chi);
        Qp[base + 0]  = f2tf(a.x * 0.125f);
        Qp[base + 4]  = f2tf(a.y * 0.125f);
        Qp[base + 8]  = f2tf(a.z * 0.125f);
        Qp[base + 12] = f2tf(a.w * 0.125f);
    }

    // ---- stage K/V chunk 0 ----
    {
#pragma unroll
        for (int i = 0; i < 4; i++) {
            float4 f = *(const float4*)(kbase + (size_t)krow * DH + 4 * b3 + 16 * i);
            uint32_t* kp = &Kq[i * 1024 + krow * 16 + b3];
            kp[(((0) + krow) & 3) * 4] = f2tf(f.x);
            kp[(((1) + krow) & 3) * 4] = f2tf(f.y);
            kp[(((2) + krow) & 3) * 4] = f2tf(f.z);
            kp[(((3) + krow) & 3) * 4] = f2tf(f.w);
        }
        const int kspv = vrow >> 4, t4v = vrow & 3, slv = (vrow >> 2) & 3;
#pragma unroll
        for (int i = 0; i < 4; i++) {
            int d0 = vcol0 + 4 * i;
            float4 f = *(const float4*)(vbase + (size_t)vrow * DH + d0);
            int tw = (t4v + ((d0 >> 2) & 3)) & 3;
            uint32_t* vp = &Vq[kspv * 1024 + d0 * 16 + tw * 4 + slv];
            vp[0]  = f2tf(f.x);
            vp[16] = f2tf(f.y);
            vp[32] = f2tf(f.z);
            vp[48] = f2tf(f.w);
        }
    }
    __syncthreads();

    float o[8][4];
#pragma unroll
    for (int nt = 0; nt < 8; nt++)
#pragma unroll
        for (int r = 0; r < 4; r++) o[nt][r] = 0.f;
    float mr0 = -1e30f, mr1 = -1e30f, l0 = 0.f, l1 = 0.f;

    const int r0g = qg0 + wrow0 + g;
    const int r1g = r0g + 8;
    const uint32_t* mrow0p = mbase + (size_t)r0g * SS;
    const uint32_t* mrow1p = mbase + (size_t)r1g * SS;

    float4 kf[4], vf[4];

    for (int kt = 0; kt < SS / 64; kt++) {
        const int kg0 = kt * 64;
        const bool more = (kt + 1) < (SS / 64);

        // prefetch next K/V chunk into regs
        if (more) {
#pragma unroll
            for (int i = 0; i < 4; i++) {
                kf[i] = *(const float4*)(kbase + (size_t)(kg0 + 64 + krow) * DH + 4 * b3 + 16 * i);
                vf[i] = *(const float4*)(vbase + (size_t)(kg0 + 64 + vrow) * DH + vcol0 + 4 * i);
            }
        }

        // prefetch masks
        uint2 mk0[8], mk1[8];
#pragma unroll
        for (int nt = 0; nt < 8; nt++) {
            int c = kg0 + nt * 8 + 2 * t4;
            mk0[nt] = *(const uint2*)(mrow0p + c);
            mk1[nt] = *(const uint2*)(mrow1p + c);
        }

        // ---- S = Q K^T ----
        float s[8][4];
#pragma unroll
        for (int nt = 0; nt < 8; nt++)
#pragma unroll
            for (int r = 0; r < 4; r++) s[nt][r] = 0.f;

#pragma unroll
        for (int ksp = 0; ksp < 4; ksp++) {
            uint4 aq0 = *(const uint4*)&Qp[((warp * 8 + 2 * ksp) * 32 + lane) * 4];
            uint4 aq1 = *(const uint4*)&Qp[((warp * 8 + 2 * ksp + 1) * 32 + lane) * 4];
            uint32_t af0[4] = {aq0.x, aq0.y, aq0.z, aq0.w};
            uint32_t af1[4] = {aq1.x, aq1.y, aq1.z, aq1.w};
#pragma unroll
            for (int nt = 0; nt < 8; nt++) {
                int n = nt * 8 + g;
                uint4 kb = *(const uint4*)&Kq[ksp * 1024 + n * 16 + ((t4 + n) & 3) * 4];
                mma8(s[nt], af0, kb.x, kb.y);
                mma8(s[nt], af1, kb.z, kb.w);
            }
        }

        // ---- mask + online softmax ----
        float M0 = -1e30f, M1 = -1e30f;
#pragma unroll
        for (int nt = 0; nt < 8; nt++) {
            if (mk0[nt].x) s[nt][0] += NEG_MASK;
            if (mk0[nt].y) s[nt][1] += NEG_MASK;
            if (mk1[nt].x) s[nt][2] += NEG_MASK;
            if (mk1[nt].y) s[nt][3] += NEG_MASK;
            M0 = fmaxf(M0, fmaxf(s[nt][0], s[nt][1]));
            M1 = fmaxf(M1, fmaxf(s[nt][2], s[nt][3]));
        }
        M0 = fmaxf(M0, __shfl_xor_sync(0xffffffffu, M0, 1));
        M0 = fmaxf(M0, __shfl_xor_sync(0xffffffffu, M0, 2));
        M1 = fmaxf(M1, __shfl_xor_sync(0xffffffffu, M1, 1));
        M1 = fmaxf(M1, __shfl_xor_sync(0xffffffffu, M1, 2));

        float mn0 = fmaxf(mr0, M0);
        float mn1 = fmaxf(mr1, M1);
        float al0 = __expf(mr0 - mn0);
        float al1 = __expf(mr1 - mn1);
        mr0 = mn0; mr1 = mn1;

        __syncwarp();
        float sum0 = 0.f, sum1 = 0.f;
#pragma unroll
        for (int nt = 0; nt < 8; nt++) {
            float p00 = __expf(s[nt][0] - mn0);
            float p01 = __expf(s[nt][1] - mn0);
            float p10 = __expf(s[nt][2] - mn1);
            float p11 = __expf(s[nt][3] - mn1);
            sum0 += p00 + p01;
            sum1 += p10 + p11;
            int c = nt * 8 + 2 * t4;
            *(uint2*)&Ps[(wrow0 + g) * PP + c]     = make_uint2(f2tf(p00), f2tf(p01));
            *(uint2*)&Ps[(wrow0 + 8 + g) * PP + c] = make_uint2(f2tf(p10), f2tf(p11));
        }
        sum0 += __shfl_xor_sync(0xffffffffu, sum0, 1);
        sum0 += __shfl_xor_sync(0xffffffffu, sum0, 2);
        sum1 += __shfl_xor_sync(0xffffffffu, sum1, 1);
        sum1 += __shfl_xor_sync(0xffffffffu, sum1, 2);
        l0 = l0 * al0 + sum0;
        l1 = l1 * al1 + sum1;

#pragma unroll
        for (int nt = 0; nt < 8; nt++) {
            o[nt][0] *= al0; o[nt][1] *= al0;
            o[nt][2] *= al1; o[nt][3] *= al1;
        }
        __syncwarp();

        // ---- O += P V ----
#pragma unroll
        for (int ksp = 0; ksp < 4; ksp++) {
            const int kc0 = 16 * ksp;
            uint32_t af0[4], af1[4];
            af0[0] = Ps[(wrow0 + g) * PP + kc0 + t4];
            af0[1] = Ps[(wrow0 + 8 + g) * PP + kc0 + t4];
            af0[2] = Ps[(wrow0 + g) * PP + kc0 + t4 + 4];
            af0[3] = Ps[(wrow0 + 8 + g) * PP + kc0 + t4 + 4];
            af1[0] = Ps[(wrow0 + g) * PP + kc0 + 8 + t4];
            af1[1] = Ps[(wrow0 + 8 + g) * PP + kc0 + 8 + t4];
            af1[2] = Ps[(wrow0 + g) * PP + kc0 + 12 + t4];
            af1[3] = Ps[(wrow0 + 8 + g) * PP + kc0 + 12 + t4];
#pragma unroll
            for (int nt = 0; nt < 8; nt++) {
                int d = nt * 8 + g;
                uint4 vb = *(const uint4*)&Vq[ksp * 1024 + d * 16 + ((t4 + ((d >> 2) & 3)) & 3) * 4];
                mma8(o[nt], af0, vb.x, vb.y);
                mma8(o[nt], af1, vb.z, vb.w);
            }
        }

        __syncthreads();   // all warps done reading Kq/Vq
        if (more) {
#pragma unroll
            for (int i = 0; i < 4; i++) {
                uint32_t* kp = &Kq[i * 1024 + krow * 16 + b3];
                kp[(((0) + krow) & 3) * 4] = f2tf(kf[i].x);
                kp[(((1) + krow) & 3) * 4] = f2tf(kf[i].y);
                kp[(((2) + krow) & 3) * 4] = f2tf(kf[i].z);
                kp[(((3) + krow) & 3) * 4] = f2tf(kf[i].w);
            }
            const int kspv = vrow >> 4, t4v = vrow & 3, slv = (vrow >> 2) & 3;
#pragma unroll
            for (int i = 0; i < 4; i++) {
                int d0 = vcol0 + 4 * i;
                int tw = (t4v + ((d0 >> 2) & 3)) & 3;
                uint32_t* vp = &Vq[kspv * 1024 + d0 * 16 + tw * 4 + slv];
                vp[0]  = f2tf(vf[i].x);
                vp[16] = f2tf(vf[i].y);
                vp[32] = f2tf(vf[i].z);
                vp[48] = f2tf(vf[i].w);
            }
            __syncthreads();
        }
    }

    // ---- epilogue ----
    float inv0 = 1.f / l0, inv1 = 1.f / l1;
    float* out0 = ctx + ((size_t)b * SS + r0g) * DM + h * DH;
    float* out1 = ctx + ((size_t)b * SS + r1g) * DM + h * DH;
#pragma unroll
    for (int nt = 0; nt < 8; nt++) {
        int c = nt * 8 + 2 * t4;
        *(float2*)(out0 + c) = make_float2(o[nt][0] * inv0, o[nt][1] * inv0);
        *(float2*)(out1 + c) = make_float2(o[nt][2] * inv1, o[nt][3] * inv1);
    }
}

// ---------------------------------------------------------------
extern "C" void kernel_launch(void* const* d_in, const int* in_sizes, int n_in,
                              void* d_out, int out_size)
{
    const float* Q  = (const float*)d_in[0];
    const float* K  = (const float*)d_in[1];
    const float* V  = (const float*)d_in[2];
    const uint32_t* mask = (const uint32_t*)d_in[3];
    const float* Wq = (const float*)d_in[4];
    const float* bq = (const float*)d_in[5];
    const float* Wk = (const float*)d_in[6];
    const float* bk = (const float*)d_in[7];
    const float* Wv = (const float*)d_in[8];
    const float* bv = (const float*)d_in[9];
    const float* Wo = (const float*)d_in[10];
    const float* bo = (const float*)d_in[11];
    float* out = (float*)d_out;

    float *qb, *kb, *vb, *ctx;
    cudaGetSymbolAddress((void**)&qb,  g_q);
    cudaGetSymbolAddress((void**)&kb,  g_k);
    cudaGetSymbolAddress((void**)&vb,  g_v);
    cudaGetSymbolAddress((void**)&ctx, g_ctx);

    dim3 gg(DM / 128, (BB * SS) / 128);
    dim3 tt(256);

    gemm_tc_kernel<<<gg, tt>>>(Q, Wq, bq, qb, 1);
    gemm_tc_kernel<<<gg, tt>>>(K, Wk, bk, kb, 1);
    gemm_tc_kernel<<<gg, tt>>>(V, Wv, bv, vb, 1);

    const int smem = ATT_SMEM_U32 * (int)sizeof(uint32_t);
    cudaFuncSetAttribute(attn_tc_kernel, cudaFuncAttributeMaxDynamicSharedMemorySize, smem);
    attn_tc_kernel<<<dim3(SS / 128, HH, BB), tt, smem>>>(qb, kb, vb, mask, ctx);

    gemm_tc_kernel<<<gg, tt>>>(ctx, Wo, bo, out, 0);
}

// round 12
// speedup vs baseline: 1.0527x; 1.0238x over previous
#include <cuda_runtime.h>
#include <cstdint>

#define BB 2
#define SS 2048
#define DM 1024
#define HH 16
#define DH 64
#define NEG_MASK (-9e10f)

__device__ float g_q[BB * HH * SS * DH];
__device__ float g_k[BB * HH * SS * DH];
__device__ float g_v[BB * HH * SS * DH];
__device__ float g_ctx[BB * SS * DM];

__device__ __forceinline__ uint32_t f2tf(float x) {
    uint32_t r;
    asm volatile("cvt.rna.tf32.f32 %0, %1;" : "=r"(r) : "f"(x));
    return r;
}

__device__ __forceinline__ void mma8(float* d, const uint32_t* a, uint32_t b0, uint32_t b1) {
    asm volatile(
        "mma.sync.aligned.m16n8k8.row.col.f32.tf32.tf32.f32 "
        "{%0,%1,%2,%3}, {%4,%5,%6,%7}, {%8,%9}, {%0,%1,%2,%3};\n"
        : "+f"(d[0]), "+f"(d[1]), "+f"(d[2]), "+f"(d[3])
        : "r"(a[0]), "r"(a[1]), "r"(a[2]), "r"(a[3]), "r"(b0), "r"(b1));
}

// ---------------------------------------------------------------
// NT GEMM (tf32, register-prefetch pipelined) — unchanged
// ---------------------------------------------------------------
#define GBK 32
#define GPAD 36

__global__ __launch_bounds__(256, 1) void gemm_tc_kernel(
    const float* __restrict__ A, const float* __restrict__ W,
    const float* __restrict__ bias, float* __restrict__ C, int split)
{
    __shared__ uint32_t As[128 * GPAD];
    __shared__ uint32_t Ws[128 * GPAD];

    const int tid  = threadIdx.x;
    const int warp = tid >> 5;
    const int lane = tid & 31;
    const int g    = lane >> 2;
    const int t4   = lane & 3;
    const int wm   = warp & 1;
    const int wn   = warp >> 1;
    const int m0   = blockIdx.y * 128;
    const int n0   = blockIdx.x * 128;

    float acc[4][4][4];
#pragma unroll
    for (int mt = 0; mt < 4; mt++)
#pragma unroll
        for (int nt = 0; nt < 4; nt++)
#pragma unroll
            for (int r = 0; r < 4; r++) acc[mt][nt][r] = 0.f;

    const float* Ap = A + (size_t)m0 * DM;
    const float* Wp = W + (size_t)n0 * DM;

#pragma unroll
    for (int i = 0; i < 4; i++) {
        int idx = tid + i * 256;
        int r   = idx >> 3;
        int c4  = (idx & 7) * 4;
        float4 a = *(const float4*)(Ap + (size_t)r * DM + c4);
        As[r * GPAD + c4 + 0] = f2tf(a.x); As[r * GPAD + c4 + 1] = f2tf(a.y);
        As[r * GPAD + c4 + 2] = f2tf(a.z); As[r * GPAD + c4 + 3] = f2tf(a.w);
        float4 w = *(const float4*)(Wp + (size_t)r * DM + c4);
        Ws[r * GPAD + c4 + 0] = f2tf(w.x); Ws[r * GPAD + c4 + 1] = f2tf(w.y);
        Ws[r * GPAD + c4 + 2] = f2tf(w.z); Ws[r * GPAD + c4 + 3] = f2tf(w.w);
    }
    __syncthreads();

    float4 pa[4], pw[4];
    for (int k0 = 0; k0 < DM; k0 += GBK) {
        const bool more = (k0 + GBK) < DM;
        if (more) {
#pragma unroll
            for (int i = 0; i < 4; i++) {
                int idx = tid + i * 256;
                int r   = idx >> 3;
                int c4  = (idx & 7) * 4;
                pa[i] = *(const float4*)(Ap + (size_t)r * DM + k0 + GBK + c4);
                pw[i] = *(const float4*)(Wp + (size_t)r * DM + k0 + GBK + c4);
            }
        }

#pragma unroll
        for (int ks = 0; ks < GBK / 8; ks++) {
            const int kc = ks * 8 + t4;
            uint32_t af[4][4];
#pragma unroll
            for (int mt = 0; mt < 4; mt++) {
                int row = wm * 64 + mt * 16 + g;
                af[mt][0] = As[row * GPAD + kc];
                af[mt][1] = As[(row + 8) * GPAD + kc];
                af[mt][2] = As[row * GPAD + kc + 4];
                af[mt][3] = As[(row + 8) * GPAD + kc + 4];
            }
#pragma unroll
            for (int nt = 0; nt < 4; nt++) {
                int col = wn * 32 + nt * 8 + g;
                uint32_t b0 = Ws[col * GPAD + kc];
                uint32_t b1 = Ws[col * GPAD + kc + 4];
#pragma unroll
                for (int mt = 0; mt < 4; mt++)
                    mma8(acc[mt][nt], af[mt], b0, b1);
            }
        }
        __syncthreads();
        if (more) {
#pragma unroll
            for (int i = 0; i < 4; i++) {
                int idx = tid + i * 256;
                int r   = idx >> 3;
                int c4  = (idx & 7) * 4;
                As[r * GPAD + c4 + 0] = f2tf(pa[i].x); As[r * GPAD + c4 + 1] = f2tf(pa[i].y);
                As[r * GPAD + c4 + 2] = f2tf(pa[i].z); As[r * GPAD + c4 + 3] = f2tf(pa[i].w);
                Ws[r * GPAD + c4 + 0] = f2tf(pw[i].x); Ws[r * GPAD + c4 + 1] = f2tf(pw[i].y);
                Ws[r * GPAD + c4 + 2] = f2tf(pw[i].z); Ws[r * GPAD + c4 + 3] = f2tf(pw[i].w);
            }
            __syncthreads();
        }
    }

#pragma unroll
    for (int mt = 0; mt < 4; mt++) {
        int r0 = m0 + wm * 64 + mt * 16 + g;
        int r1 = r0 + 8;
#pragma unroll
        for (int nt = 0; nt < 4; nt++) {
            int c = n0 + wn * 32 + nt * 8 + 2 * t4;
            float2 bi = *(const float2*)(bias + c);
            float v00 = acc[mt][nt][0] + bi.x;
            float v01 = acc[mt][nt][1] + bi.y;
            float v10 = acc[mt][nt][2] + bi.x;
            float v11 = acc[mt][nt][3] + bi.y;
            if (split) {
                int h  = c >> 6;
                int dh = c & 63;
                int b0i = r0 >> 11, s0 = r0 & 2047;
                int b1i = r1 >> 11, s1 = r1 & 2047;
                float* p0 = (float*)C + (((size_t)b0i * HH + h) * SS + s0) * DH + dh;
                float* p1 = (float*)C + (((size_t)b1i * HH + h) * SS + s1) * DH + dh;
                p0[0] = v00; p0[1] = v01;
                p1[0] = v10; p1[1] = v11;
            } else {
                *(float2*)(C + (size_t)r0 * DM + c) = make_float2(v00, v01);
                *(float2*)(C + (size_t)r1 * DM + c) = make_float2(v10, v11);
            }
        }
    }
}

// ---------------------------------------------------------------
// Flash attention (tf32). Packed conflict-free smem layouts
// (round-10), register diet + forced 2 CTAs/SM for latency hiding.
// ---------------------------------------------------------------
#define PP 76
#define ATT_SMEM_U32 (8192 + 4096 + 4096 + 128 * PP)

__global__ __launch_bounds__(256, 2) void attn_tc_kernel(
    const float* __restrict__ q, const float* __restrict__ k,
    const float* __restrict__ v, const uint32_t* __restrict__ mask,
    float* __restrict__ ctx)
{
    extern __shared__ uint32_t su[];
    uint32_t* Qp = su;
    uint32_t* Kq = Qp + 8192;
    uint32_t* Vq = Kq + 4096;
    uint32_t* Ps = Vq + 4096;

    const int tid  = threadIdx.x;
    const int warp = tid >> 5;
    const int lane = tid & 31;
    const int g    = lane >> 2;
    const int t4   = lane & 3;
    const int a7   = lane & 7;
    const int b3   = lane >> 3;
    const int qg0  = blockIdx.x * 128;
    const int h    = blockIdx.y;
    const int b    = blockIdx.z;
    const int wrow0 = warp * 16;

    // staging maps
    const int krow  = 8 * warp + a7;
    const int vrow  = 16 * (warp & 3) + (lane >> 1);
    const int vcol0 = 32 * (warp >> 2) + 16 * (lane & 1);

    const float* qptr  = q + (((size_t)b * HH + h) * SS + qg0) * DH;
    const float* kbase = k + (((size_t)b * HH + h) * SS) * DH;
    const float* vbase = v + (((size_t)b * HH + h) * SS) * DH;
    const uint32_t* mbase = mask + (size_t)b * SS * SS;

    // ---- stage Q (packed A-frag layout), scaled ----
#pragma unroll
    for (int i = 0; i < 8; i++) {
        int idx = tid + i * 256;
        int r   = idx >> 4;
        int c0  = (idx & 15) * 4;
        float4 a = *(const float4*)(qptr + (size_t)r * DH + c0);
        int blk = r >> 4, gg = r & 7, half = (r >> 3) & 1;
        int ks  = c0 >> 3, chi = (c0 >> 2) & 1;
        int base = ((blk * 8 + ks) * 32 + 4 * gg) * 4 + (half + 2 * chi);
        Qp[base + 0]  = f2tf(a.x * 0.125f);
        Qp[base + 4]  = f2tf(a.y * 0.125f);
        Qp[base + 8]  = f2tf(a.z * 0.125f);
        Qp[base + 12] = f2tf(a.w * 0.125f);
    }

    // ---- stage K/V chunk 0 ----
    {
#pragma unroll
        for (int i = 0; i < 4; i++) {
            float4 f = *(const float4*)(kbase + (size_t)krow * DH + 4 * b3 + 16 * i);
            uint32_t* kp = &Kq[i * 1024 + krow * 16 + b3];
            kp[(((0) + krow) & 3) * 4] = f2tf(f.x);
            kp[(((1) + krow) & 3) * 4] = f2tf(f.y);
            kp[(((2) + krow) & 3) * 4] = f2tf(f.z);
            kp[(((3) + krow) & 3) * 4] = f2tf(f.w);
        }
        const int kspv = vrow >> 4, t4v = vrow & 3, slv = (vrow >> 2) & 3;
#pragma unroll
        for (int i = 0; i < 4; i++) {
            int d0 = vcol0 + 4 * i;
            float4 f = *(const float4*)(vbase + (size_t)vrow * DH + d0);
            int tw = (t4v + ((d0 >> 2) & 3)) & 3;
            uint32_t* vp = &Vq[kspv * 1024 + d0 * 16 + tw * 4 + slv];
            vp[0]  = f2tf(f.x);
            vp[16] = f2tf(f.y);
            vp[32] = f2tf(f.z);
            vp[48] = f2tf(f.w);
        }
    }
    __syncthreads();

    float o[8][4];
#pragma unroll
    for (int nt = 0; nt < 8; nt++)
#pragma unroll
        for (int r = 0; r < 4; r++) o[nt][r] = 0.f;
    float mr0 = -1e30f, mr1 = -1e30f, l0 = 0.f, l1 = 0.f;

    const int r0g = qg0 + wrow0 + g;
    const int r1g = r0g + 8;
    const uint32_t* mrow0p = mbase + (size_t)r0g * SS;
    const uint32_t* mrow1p = mbase + (size_t)r1g * SS;

    for (int kt = 0; kt < SS / 64; kt++) {
        const int kg0 = kt * 64;
        const bool more = (kt + 1) < (SS / 64);

        // ---- S = Q K^T ----
        float s[8][4];
#pragma unroll
        for (int nt = 0; nt < 8; nt++)
#pragma unroll
            for (int r = 0; r < 4; r++) s[nt][r] = 0.f;

#pragma unroll
        for (int ksp = 0; ksp < 4; ksp++) {
            uint4 aq0 = *(const uint4*)&Qp[((warp * 8 + 2 * ksp) * 32 + lane) * 4];
            uint4 aq1 = *(const uint4*)&Qp[((warp * 8 + 2 * ksp + 1) * 32 + lane) * 4];
            uint32_t af0[4] = {aq0.x, aq0.y, aq0.z, aq0.w};
            uint32_t af1[4] = {aq1.x, aq1.y, aq1.z, aq1.w};
#pragma unroll
            for (int nt = 0; nt < 8; nt++) {
                int n = nt * 8 + g;
                uint4 kb = *(const uint4*)&Kq[ksp * 1024 + n * 16 + ((t4 + n) & 3) * 4];
                mma8(s[nt], af0, kb.x, kb.y);
                mma8(s[nt], af1, kb.z, kb.w);
            }
        }

        // ---- mask + online softmax (inline mask loads) ----
        float M0 = -1e30f, M1 = -1e30f;
#pragma unroll
        for (int nt = 0; nt < 8; nt++) {
            int c = kg0 + nt * 8 + 2 * t4;
            uint2 mk0 = *(const uint2*)(mrow0p + c);
            uint2 mk1 = *(const uint2*)(mrow1p + c);
            if (mk0.x) s[nt][0] += NEG_MASK;
            if (mk0.y) s[nt][1] += NEG_MASK;
            if (mk1.x) s[nt][2] += NEG_MASK;
            if (mk1.y) s[nt][3] += NEG_MASK;
            M0 = fmaxf(M0, fmaxf(s[nt][0], s[nt][1]));
            M1 = fmaxf(M1, fmaxf(s[nt][2], s[nt][3]));
        }
        M0 = fmaxf(M0, __shfl_xor_sync(0xffffffffu, M0, 1));
        M0 = fmaxf(M0, __shfl_xor_sync(0xffffffffu, M0, 2));
        M1 = fmaxf(M1, __shfl_xor_sync(0xffffffffu, M1, 1));
        M1 = fmaxf(M1, __shfl_xor_sync(0xffffffffu, M1, 2));

        float mn0 = fmaxf(mr0, M0);
        float mn1 = fmaxf(mr1, M1);
        float al0 = __expf(mr0 - mn0);
        float al1 = __expf(mr1 - mn1);
        mr0 = mn0; mr1 = mn1;

        __syncwarp();
        float sum0 = 0.f, sum1 = 0.f;
#pragma unroll
        for (int nt = 0; nt < 8; nt++) {
            float p00 = __expf(s[nt][0] - mn0);
            float p01 = __expf(s[nt][1] - mn0);
            float p10 = __expf(s[nt][2] - mn1);
            float p11 = __expf(s[nt][3] - mn1);
            sum0 += p00 + p01;
            sum1 += p10 + p11;
            int c = nt * 8 + 2 * t4;
            *(uint2*)&Ps[(wrow0 + g) * PP + c]     = make_uint2(f2tf(p00), f2tf(p01));
            *(uint2*)&Ps[(wrow0 + 8 + g) * PP + c] = make_uint2(f2tf(p10), f2tf(p11));
        }
        sum0 += __shfl_xor_sync(0xffffffffu, sum0, 1);
        sum0 += __shfl_xor_sync(0xffffffffu, sum0, 2);
        sum1 += __shfl_xor_sync(0xffffffffu, sum1, 1);
        sum1 += __shfl_xor_sync(0xffffffffu, sum1, 2);
        l0 = l0 * al0 + sum0;
        l1 = l1 * al1 + sum1;

#pragma unroll
        for (int nt = 0; nt < 8; nt++) {
            o[nt][0] *= al0; o[nt][1] *= al0;
            o[nt][2] *= al1; o[nt][3] *= al1;
        }
        __syncwarp();

        // ---- O += P V ----
#pragma unroll
        for (int ksp = 0; ksp < 4; ksp++) {
            const int kc0 = 16 * ksp;
            uint32_t af0[4], af1[4];
            af0[0] = Ps[(wrow0 + g) * PP + kc0 + t4];
            af0[1] = Ps[(wrow0 + 8 + g) * PP + kc0 + t4];
            af0[2] = Ps[(wrow0 + g) * PP + kc0 + t4 + 4];
            af0[3] = Ps[(wrow0 + 8 + g) * PP + kc0 + t4 + 4];
            af1[0] = Ps[(wrow0 + g) * PP + kc0 + 8 + t4];
            af1[1] = Ps[(wrow0 + 8 + g) * PP + kc0 + 8 + t4];
            af1[2] = Ps[(wrow0 + g) * PP + kc0 + 12 + t4];
            af1[3] = Ps[(wrow0 + 8 + g) * PP + kc0 + 12 + t4];
#pragma unroll
            for (int nt = 0; nt < 8; nt++) {
                int d = nt * 8 + g;
                uint4 vb = *(const uint4*)&Vq[ksp * 1024 + d * 16 + ((t4 + ((d >> 2) & 3)) & 3) * 4];
                mma8(o[nt], af0, vb.x, vb.y);
                mma8(o[nt], af1, vb.z, vb.w);
            }
        }

        __syncthreads();   // all warps done reading Kq/Vq
        if (more) {
            // stage next chunk inline (2 CTAs/SM hide the LDG latency)
#pragma unroll
            for (int i = 0; i < 4; i++) {
                float4 f = *(const float4*)(kbase + (size_t)(kg0 + 64 + krow) * DH + 4 * b3 + 16 * i);
                uint32_t* kp = &Kq[i * 1024 + krow * 16 + b3];
                kp[(((0) + krow) & 3) * 4] = f2tf(f.x);
                kp[(((1) + krow) & 3) * 4] = f2tf(f.y);
                kp[(((2) + krow) & 3) * 4] = f2tf(f.z);
                kp[(((3) + krow) & 3) * 4] = f2tf(f.w);
            }
            const int kspv = vrow >> 4, t4v = vrow & 3, slv = (vrow >> 2) & 3;
#pragma unroll
            for (int i = 0; i < 4; i++) {
                int d0 = vcol0 + 4 * i;
                float4 f = *(const float4*)(vbase + (size_t)(kg0 + 64 + vrow) * DH + d0);
                int tw = (t4v + ((d0 >> 2) & 3)) & 3;
                uint32_t* vp = &Vq[kspv * 1024 + d0 * 16 + tw * 4 + slv];
                vp[0]  = f2tf(f.x);
                vp[16] = f2tf(f.y);
                vp[32] = f2tf(f.z);
                vp[48] = f2tf(f.w);
            }
            __syncthreads();
        }
    }

    // ---- epilogue ----
    float inv0 = 1.f / l0, inv1 = 1.f / l1;
    float* out0 = ctx + ((size_t)b * SS + r0g) * DM + h * DH;
    float* out1 = ctx + ((size_t)b * SS + r1g) * DM + h * DH;
#pragma unroll
    for (int nt = 0; nt < 8; nt++) {
        int c = nt * 8 + 2 * t4;
        *(float2*)(out0 + c) = make_float2(o[nt][0] * inv0, o[nt][1] * inv0);
        *(float2*)(out1 + c) = make_float2(o[nt][2] * inv1, o[nt][3] * inv1);
    }
}

// ---------------------------------------------------------------
extern "C" void kernel_launch(void* const* d_in, const int* in_sizes, int n_in,
                              void* d_out, int out_size)
{
    const float* Q  = (const float*)d_in[0];
    const float* K  = (const float*)d_in[1];
    const float* V  = (const float*)d_in[2];
    const uint32_t* mask = (const uint32_t*)d_in[3];
    const float* Wq = (const float*)d_in[4];
    const float* bq = (const float*)d_in[5];
    const float* Wk = (const float*)d_in[6];
    const float* bk = (const float*)d_in[7];
    const float* Wv = (const float*)d_in[8];
    const float* bv = (const float*)d_in[9];
    const float* Wo = (const float*)d_in[10];
    const float* bo = (const float*)d_in[11];
    float* out = (float*)d_out;

    float *qb, *kb, *vb, *ctx;
    cudaGetSymbolAddress((void**)&qb,  g_q);
    cudaGetSymbolAddress((void**)&kb,  g_k);
    cudaGetSymbolAddress((void**)&vb,  g_v);
    cudaGetSymbolAddress((void**)&ctx, g_ctx);

    dim3 gg(DM / 128, (BB * SS) / 128);
    dim3 tt(256);

    gemm_tc_kernel<<<gg, tt>>>(Q, Wq, bq, qb, 1);
    gemm_tc_kernel<<<gg, tt>>>(K, Wk, bk, kb, 1);
    gemm_tc_kernel<<<gg, tt>>>(V, Wv, bv, vb, 1);

    const int smem = ATT_SMEM_U32 * (int)sizeof(uint32_t);
    cudaFuncSetAttribute(attn_tc_kernel, cudaFuncAttributeMaxDynamicSharedMemorySize, smem);
    attn_tc_kernel<<<dim3(SS / 128, HH, BB), tt, smem>>>(qb, kb, vb, mask, ctx);

    gemm_tc_kernel<<<gg, tt>>>(ctx, Wo, bo, out, 0);
}

// round 15
// speedup vs baseline: 1.1176x; 1.0617x over previous
#include <cuda_runtime.h>
#include <cstdint>

#define BB 2
#define SS 2048
#define DM 1024
#define HH 16
#define DH 64
#define NEG_MASK (-9e10f)

__device__ float g_q[BB * HH * SS * DH];
__device__ float g_k[BB * HH * SS * DH];
__device__ float g_v[BB * HH * SS * DH];
__device__ float g_ctx[BB * SS * DM];

__device__ __forceinline__ uint32_t f2tf(float x) {
    uint32_t r;
    asm volatile("cvt.rna.tf32.f32 %0, %1;" : "=r"(r) : "f"(x));
    return r;
}

__device__ __forceinline__ void mma8(float* d, const uint32_t* a, uint32_t b0, uint32_t b1) {
    asm volatile(
        "mma.sync.aligned.m16n8k8.row.col.f32.tf32.tf32.f32 "
        "{%0,%1,%2,%3}, {%4,%5,%6,%7}, {%8,%9}, {%0,%1,%2,%3};\n"
        : "+f"(d[0]), "+f"(d[1]), "+f"(d[2]), "+f"(d[3])
        : "r"(a[0]), "r"(a[1]), "r"(a[2]), "r"(a[3]), "r"(b0), "r"(b1));
}

// ---------------------------------------------------------------
// NT GEMM (tf32), 2 CTAs/SM, no reg prefetch. blockIdx.z selects
// operand set (QKV fused launch uses z=0..2; O-proj uses z=0).
// ---------------------------------------------------------------
#define GBK 32
#define GPAD 36

__global__ __launch_bounds__(256, 2) void gemm_tc_kernel(
    const float* __restrict__ A0, const float* __restrict__ A1, const float* __restrict__ A2,
    const float* __restrict__ W0, const float* __restrict__ W1, const float* __restrict__ W2,
    const float* __restrict__ b0p, const float* __restrict__ b1p, const float* __restrict__ b2p,
    float* __restrict__ C0, float* __restrict__ C1, float* __restrict__ C2,
    int split)
{
    __shared__ uint32_t As[128 * GPAD];
    __shared__ uint32_t Ws[128 * GPAD];

    const float* A; const float* W; const float* bias; float* C;
    if (blockIdx.z == 0)      { A = A0; W = W0; bias = b0p; C = C0; }
    else if (blockIdx.z == 1) { A = A1; W = W1; bias = b1p; C = C1; }
    else                      { A = A2; W = W2; bias = b2p; C = C2; }

    const int tid  = threadIdx.x;
    const int warp = tid >> 5;
    const int lane = tid & 31;
    const int g    = lane >> 2;
    const int t4   = lane & 3;
    const int wm   = warp & 1;
    const int wn   = warp >> 1;
    const int m0   = blockIdx.y * 128;
    const int n0   = blockIdx.x * 128;

    float acc[4][4][4];
#pragma unroll
    for (int mt = 0; mt < 4; mt++)
#pragma unroll
        for (int nt = 0; nt < 4; nt++)
#pragma unroll
            for (int r = 0; r < 4; r++) acc[mt][nt][r] = 0.f;

    const float* Ap = A + (size_t)m0 * DM;
    const float* Wp = W + (size_t)n0 * DM;

    for (int k0 = 0; k0 < DM; k0 += GBK) {
#pragma unroll
        for (int i = 0; i < 4; i++) {
            int idx = tid + i * 256;
            int r   = idx >> 3;
            int c4  = (idx & 7) * 4;
            float4 a = *(const float4*)(Ap + (size_t)r * DM + k0 + c4);
            As[r * GPAD + c4 + 0] = f2tf(a.x); As[r * GPAD + c4 + 1] = f2tf(a.y);
            As[r * GPAD + c4 + 2] = f2tf(a.z); As[r * GPAD + c4 + 3] = f2tf(a.w);
            float4 w = *(const float4*)(Wp + (size_t)r * DM + k0 + c4);
            Ws[r * GPAD + c4 + 0] = f2tf(w.x); Ws[r * GPAD + c4 + 1] = f2tf(w.y);
            Ws[r * GPAD + c4 + 2] = f2tf(w.z); Ws[r * GPAD + c4 + 3] = f2tf(w.w);
        }
        __syncthreads();

#pragma unroll
        for (int ks = 0; ks < GBK / 8; ks++) {
            const int kc = ks * 8 + t4;
            uint32_t af[4][4];
#pragma unroll
            for (int mt = 0; mt < 4; mt++) {
                int row = wm * 64 + mt * 16 + g;
                af[mt][0] = As[row * GPAD + kc];
                af[mt][1] = As[(row + 8) * GPAD + kc];
                af[mt][2] = As[row * GPAD + kc + 4];
                af[mt][3] = As[(row + 8) * GPAD + kc + 4];
            }
#pragma unroll
            for (int nt = 0; nt < 4; nt++) {
                int col = wn * 32 + nt * 8 + g;
                uint32_t b0 = Ws[col * GPAD + kc];
                uint32_t b1 = Ws[col * GPAD + kc + 4];
#pragma unroll
                for (int mt = 0; mt < 4; mt++)
                    mma8(acc[mt][nt], af[mt], b0, b1);
            }
        }
        __syncthreads();
    }

#pragma unroll
    for (int mt = 0; mt < 4; mt++) {
        int r0 = m0 + wm * 64 + mt * 16 + g;
        int r1 = r0 + 8;
#pragma unroll
        for (int nt = 0; nt < 4; nt++) {
            int c = n0 + wn * 32 + nt * 8 + 2 * t4;
            float2 bi = *(const float2*)(bias + c);
            float v00 = acc[mt][nt][0] + bi.x;
            float v01 = acc[mt][nt][1] + bi.y;
            float v10 = acc[mt][nt][2] + bi.x;
            float v11 = acc[mt][nt][3] + bi.y;
            if (split) {
                int h  = c >> 6;
                int dh = c & 63;
                int b0i = r0 >> 11, s0 = r0 & 2047;
                int b1i = r1 >> 11, s1 = r1 & 2047;
                float* p0 = (float*)C + (((size_t)b0i * HH + h) * SS + s0) * DH + dh;
                float* p1 = (float*)C + (((size_t)b1i * HH + h) * SS + s1) * DH + dh;
                p0[0] = v00; p0[1] = v01;
                p1[0] = v10; p1[1] = v11;
            } else {
                *(float2*)(C + (size_t)r0 * DM + c) = make_float2(v00, v01);
                *(float2*)(C + (size_t)r1 * DM + c) = make_float2(v10, v11);
            }
        }
    }
}

// ---------------------------------------------------------------
// Flash attention (tf32) — unchanged from round 12 best.
// ---------------------------------------------------------------
#define PP 76
#define ATT_SMEM_U32 (8192 + 4096 + 4096 + 128 * PP)

__global__ __launch_bounds__(256, 2) void attn_tc_kernel(
    const float* __restrict__ q, const float* __restrict__ k,
    const float* __restrict__ v, const uint32_t* __restrict__ mask,
    float* __restrict__ ctx)
{
    extern __shared__ uint32_t su[];
    uint32_t* Qp = su;
    uint32_t* Kq = Qp + 8192;
    uint32_t* Vq = Kq + 4096;
    uint32_t* Ps = Vq + 4096;

    const int tid  = threadIdx.x;
    const int warp = tid >> 5;
    const int lane = tid & 31;
    const int g    = lane >> 2;
    const int t4   = lane & 3;
    const int a7   = lane & 7;
    const int b3   = lane >> 3;
    const int qg0  = blockIdx.x * 128;
    const int h    = blockIdx.y;
    const int b    = blockIdx.z;
    const int wrow0 = warp * 16;

    const int krow  = 8 * warp + a7;
    const int vrow  = 16 * (warp & 3) + (lane >> 1);
    const int vcol0 = 32 * (warp >> 2) + 16 * (lane & 1);

    const float* qptr  = q + (((size_t)b * HH + h) * SS + qg0) * DH;
    const float* kbase = k + (((size_t)b * HH + h) * SS) * DH;
    const float* vbase = v + (((size_t)b * HH + h) * SS) * DH;
    const uint32_t* mbase = mask + (size_t)b * SS * SS;

#pragma unroll
    for (int i = 0; i < 8; i++) {
        int idx = tid + i * 256;
        int r   = idx >> 4;
        int c0  = (idx & 15) * 4;
        float4 a = *(const float4*)(qptr + (size_t)r * DH + c0);
        int blk = r >> 4, gg = r & 7, half = (r >> 3) & 1;
        int ks  = c0 >> 3, chi = (c0 >> 2) & 1;
        int base = ((blk * 8 + ks) * 32 + 4 * gg) * 4 + (half + 2 * chi);
        Qp[base + 0]  = f2tf(a.x * 0.125f);
        Qp[base + 4]  = f2tf(a.y * 0.125f);
        Qp[base + 8]  = f2tf(a.z * 0.125f);
        Qp[base + 12] = f2tf(a.w * 0.125f);
    }

    {
#pragma unroll
        for (int i = 0; i < 4; i++) {
            float4 f = *(const float4*)(kbase + (size_t)krow * DH + 4 * b3 + 16 * i);
            uint32_t* kp = &Kq[i * 1024 + krow * 16 + b3];
            kp[(((0) + krow) & 3) * 4] = f2tf(f.x);
            kp[(((1) + krow) & 3) * 4] = f2tf(f.y);
            kp[(((2) + krow) & 3) * 4] = f2tf(f.z);
            kp[(((3) + krow) & 3) * 4] = f2tf(f.w);
        }
        const int kspv = vrow >> 4, t4v = vrow & 3, slv = (vrow >> 2) & 3;
#pragma unroll
        for (int i = 0; i < 4; i++) {
            int d0 = vcol0 + 4 * i;
            float4 f = *(const float4*)(vbase + (size_t)vrow * DH + d0);
            int tw = (t4v + ((d0 >> 2) & 3)) & 3;
            uint32_t* vp = &Vq[kspv * 1024 + d0 * 16 + tw * 4 + slv];
            vp[0]  = f2tf(f.x);
            vp[16] = f2tf(f.y);
            vp[32] = f2tf(f.z);
            vp[48] = f2tf(f.w);
        }
    }
    __syncthreads();

    float o[8][4];
#pragma unroll
    for (int nt = 0; nt < 8; nt++)
#pragma unroll
        for (int r = 0; r < 4; r++) o[nt][r] = 0.f;
    float mr0 = -1e30f, mr1 = -1e30f, l0 = 0.f, l1 = 0.f;

    const int r0g = qg0 + wrow0 + g;
    const int r1g = r0g + 8;
    const uint32_t* mrow0p = mbase + (size_t)r0g * SS;
    const uint32_t* mrow1p = mbase + (size_t)r1g * SS;

    for (int kt = 0; kt < SS / 64; kt++) {
        const int kg0 = kt * 64;
        const bool more = (kt + 1) < (SS / 64);

        float s[8][4];
#pragma unroll
        for (int nt = 0; nt < 8; nt++)
#pragma unroll
            for (int r = 0; r < 4; r++) s[nt][r] = 0.f;

#pragma unroll
        for (int ksp = 0; ksp < 4; ksp++) {
            uint4 aq0 = *(const uint4*)&Qp[((warp * 8 + 2 * ksp) * 32 + lane) * 4];
            uint4 aq1 = *(const uint4*)&Qp[((warp * 8 + 2 * ksp + 1) * 32 + lane) * 4];
            uint32_t af0[4] = {aq0.x, aq0.y, aq0.z, aq0.w};
            uint32_t af1[4] = {aq1.x, aq1.y, aq1.z, aq1.w};
#pragma unroll
            for (int nt = 0; nt < 8; nt++) {
                int n = nt * 8 + g;
                uint4 kb = *(const uint4*)&Kq[ksp * 1024 + n * 16 + ((t4 + n) & 3) * 4];
                mma8(s[nt], af0, kb.x, kb.y);
                mma8(s[nt], af1, kb.z, kb.w);
            }
        }

        float M0 = -1e30f, M1 = -1e30f;
#pragma unroll
        for (int nt = 0; nt < 8; nt++) {
            int c = kg0 + nt * 8 + 2 * t4;
            uint2 mk0 = *(const uint2*)(mrow0p + c);
            uint2 mk1 = *(const uint2*)(mrow1p + c);
            if (mk0.x) s[nt][0] += NEG_MASK;
            if (mk0.y) s[nt][1] += NEG_MASK;
            if (mk1.x) s[nt][2] += NEG_MASK;
            if (mk1.y) s[nt][3] += NEG_MASK;
            M0 = fmaxf(M0, fmaxf(s[nt][0], s[nt][1]));
            M1 = fmaxf(M1, fmaxf(s[nt][2], s[nt][3]));
        }
        M0 = fmaxf(M0, __shfl_xor_sync(0xffffffffu, M0, 1));
        M0 = fmaxf(M0, __shfl_xor_sync(0xffffffffu, M0, 2));
        M1 = fmaxf(M1, __shfl_xor_sync(0xffffffffu, M1, 1));
        M1 = fmaxf(M1, __shfl_xor_sync(0xffffffffu, M1, 2));

        float mn0 = fmaxf(mr0, M0);
        float mn1 = fmaxf(mr1, M1);
        float al0 = __expf(mr0 - mn0);
        float al1 = __expf(mr1 - mn1);
        mr0 = mn0; mr1 = mn1;

        __syncwarp();
        float sum0 = 0.f, sum1 = 0.f;
#pragma unroll
        for (int nt = 0; nt < 8; nt++) {
            float p00 = __expf(s[nt][0] - mn0);
            float p01 = __expf(s[nt][1] - mn0);
            float p10 = __expf(s[nt][2] - mn1);
            float p11 = __expf(s[nt][3] - mn1);
            sum0 += p00 + p01;
            sum1 += p10 + p11;
            int c = nt * 8 + 2 * t4;
            *(uint2*)&Ps[(wrow0 + g) * PP + c]     = make_uint2(f2tf(p00), f2tf(p01));
            *(uint2*)&Ps[(wrow0 + 8 + g) * PP + c] = make_uint2(f2tf(p10), f2tf(p11));
        }
        sum0 += __shfl_xor_sync(0xffffffffu, sum0, 1);
        sum0 += __shfl_xor_sync(0xffffffffu, sum0, 2);
        sum1 += __shfl_xor_sync(0xffffffffu, sum1, 1);
        sum1 += __shfl_xor_sync(0xffffffffu, sum1, 2);
        l0 = l0 * al0 + sum0;
        l1 = l1 * al1 + sum1;

#pragma unroll
        for (int nt = 0; nt < 8; nt++) {
            o[nt][0] *= al0; o[nt][1] *= al0;
            o[nt][2] *= al1; o[nt][3] *= al1;
        }
        __syncwarp();

#pragma unroll
        for (int ksp = 0; ksp < 4; ksp++) {
            const int kc0 = 16 * ksp;
            uint32_t af0[4], af1[4];
            af0[0] = Ps[(wrow0 + g) * PP + kc0 + t4];
            af0[1] = Ps[(wrow0 + 8 + g) * PP + kc0 + t4];
            af0[2] = Ps[(wrow0 + g) * PP + kc0 + t4 + 4];
            af0[3] = Ps[(wrow0 + 8 + g) * PP + kc0 + t4 + 4];
            af1[0] = Ps[(wrow0 + g) * PP + kc0 + 8 + t4];
            af1[1] = Ps[(wrow0 + 8 + g) * PP + kc0 + 8 + t4];
            af1[2] = Ps[(wrow0 + g) * PP + kc0 + 12 + t4];
            af1[3] = Ps[(wrow0 + 8 + g) * PP + kc0 + 12 + t4];
#pragma unroll
            for (int nt = 0; nt < 8; nt++) {
                int d = nt * 8 + g;
                uint4 vb = *(const uint4*)&Vq[ksp * 1024 + d * 16 + ((t4 + ((d >> 2) & 3)) & 3) * 4];
                mma8(o[nt], af0, vb.x, vb.y);
                mma8(o[nt], af1, vb.z, vb.w);
            }
        }

        __syncthreads();
        if (more) {
#pragma unroll
            for (int i = 0; i < 4; i++) {
                float4 f = *(const float4*)(kbase + (size_t)(kg0 + 64 + krow) * DH + 4 * b3 + 16 * i);
                uint32_t* kp = &Kq[i * 1024 + krow * 16 + b3];
                kp[(((0) + krow) & 3) * 4] = f2tf(f.x);
                kp[(((1) + krow) & 3) * 4] = f2tf(f.y);
                kp[(((2) + krow) & 3) * 4] = f2tf(f.z);
                kp[(((3) + krow) & 3) * 4] = f2tf(f.w);
            }
            const int kspv = vrow >> 4, t4v = vrow & 3, slv = (vrow >> 2) & 3;
#pragma unroll
            for (int i = 0; i < 4; i++) {
                int d0 = vcol0 + 4 * i;
                float4 f = *(const float4*)(vbase + (size_t)(kg0 + 64 + vrow) * DH + d0);
                int tw = (t4v + ((d0 >> 2) & 3)) & 3;
                uint32_t* vp = &Vq[kspv * 1024 + d0 * 16 + tw * 4 + slv];
                vp[0]  = f2tf(f.x);
                vp[16] = f2tf(f.y);
                vp[32] = f2tf(f.z);
                vp[48] = f2tf(f.w);
            }
            __syncthreads();
        }
    }

    float inv0 = 1.f / l0, inv1 = 1.f / l1;
    float* out0 = ctx + ((size_t)b * SS + r0g) * DM + h * DH;
    float* out1 = ctx + ((size_t)b * SS + r1g) * DM + h * DH;
#pragma unroll
    for (int nt = 0; nt < 8; nt++) {
        int c = nt * 8 + 2 * t4;
        *(float2*)(out0 + c) = make_float2(o[nt][0] * inv0, o[nt][1] * inv0);
        *(float2*)(out1 + c) = make_float2(o[nt][2] * inv1, o[nt][3] * inv1);
    }
}

// ---------------------------------------------------------------
extern "C" void kernel_launch(void* const* d_in, const int* in_sizes, int n_in,
                              void* d_out, int out_size)
{
    const float* Q  = (const float*)d_in[0];
    const float* K  = (const float*)d_in[1];
    const float* V  = (const float*)d_in[2];
    const uint32_t* mask = (const uint32_t*)d_in[3];
    const float* Wq = (const float*)d_in[4];
    const float* bq = (const float*)d_in[5];
    const float* Wk = (const float*)d_in[6];
    const float* bk = (const float*)d_in[7];
    const float* Wv = (const float*)d_in[8];
    const float* bv = (const float*)d_in[9];
    const float* Wo = (const float*)d_in[10];
    const float* bo = (const float*)d_in[11];
    float* out = (float*)d_out;

    float *qb, *kb, *vb, *ctx;
    cudaGetSymbolAddress((void**)&qb,  g_q);
    cudaGetSymbolAddress((void**)&kb,  g_k);
    cudaGetSymbolAddress((void**)&vb,  g_v);
    cudaGetSymbolAddress((void**)&ctx, g_ctx);

    dim3 tt(256);

    // fused QKV projections: one launch, z selects operand set
    gemm_tc_kernel<<<dim3(DM / 128, (BB * SS) / 128, 3), tt>>>(
        Q, K, V, Wq, Wk, Wv, bq, bk, bv, qb, kb, vb, 1);

    const int smem = ATT_SMEM_U32 * (int)sizeof(uint32_t);
    cudaFuncSetAttribute(attn_tc_kernel, cudaFuncAttributeMaxDynamicSharedMemorySize, smem);
    attn_tc_kernel<<<dim3(SS / 128, HH, BB), tt, smem>>>(qb, kb, vb, mask, ctx);

    // O projection
    gemm_tc_kernel<<<dim3(DM / 128, (BB * SS) / 128, 1), tt>>>(
        ctx, ctx, ctx, Wo, Wo, Wo, bo, bo, bo, out, out, out, 0);
}